// round 11
// baseline (speedup 1.0000x reference)
#include <cuda_runtime.h>
#include <cuda_fp16.h>
#include <mma.h>
#include <math.h>

using namespace nvcuda;

#define N_NODES 10000
#define N_EDGES 640000
#define D 128
#define K2 256           // GEMM K = 2*D  ([agg | self] @ [Wl ; Wr])
#define CAP 256          // per-node bucket capacity (max deg ~100 for this dist)
#define OVF_MAX 8192
#define TILE 16          // rows per fused block
#define NTHREADS 128

// ---------------- scratch (no allocations allowed) ----------------
__device__ int     g_cnt[N_NODES];
__device__ int     g_bucket[N_NODES * CAP];
__device__ int     g_ovf_cnt;
__device__ int     g_ovf[OVF_MAX * 2];       // (src,dst) pairs that overflowed
__device__ float   g_h1[N_NODES * D];
__device__ __half2 g_xh[N_NODES * (D / 2)];  // half-precision gather staging
__device__ __half  g_Whi[2][K2 * D];         // [Wl;Wr] hi halves, per layer
__device__ __half  g_Wlo[2][K2 * D];         // residual lo halves

// ---------------- single-pass bucket scatter ----------------
__global__ void zero_kernel(int n) {
    int i = blockIdx.x * blockDim.x + threadIdx.x;
    if (i < n) g_cnt[i] = 0;
    if (i == 0) g_ovf_cnt = 0;
}

__global__ void scatter_kernel(const int* __restrict__ ei, int E, int n) {
    int e = blockIdx.x * blockDim.x + threadIdx.x;
    if (e < E) {
        int s = ei[e];       // src row
        int d = ei[E + e];   // dst row
        if (s >= 0 && s < n && d >= 0 && d < n) {
            int p = atomicAdd(&g_cnt[d], 1);
            if (p < CAP) {
                g_bucket[d * CAP + p] = s;
            } else {
                int q = atomicAdd(&g_ovf_cnt, 1);
                if (q < OVF_MAX) { g_ovf[2 * q] = s; g_ovf[2 * q + 1] = d; }
            }
        }
    }
}

// ---------------- weight split fp32 -> (hi, lo) halves, both layers ----------------
__global__ void convert_w_kernel(const float* __restrict__ Wl0, const float* __restrict__ Wr0,
                                 const float* __restrict__ Wl1, const float* __restrict__ Wr1) {
    int i = blockIdx.x * blockDim.x + threadIdx.x;   // 0 .. 2*256*128-1
    if (i >= 2 * K2 * D) return;
    int layer = i >> 15;           // /(256*128)
    int rc    = i & 32767;
    int r     = rc >> 7;           // 0..255
    int c     = rc & 127;
    const float* W = (layer == 0) ? (r < D ? Wl0 : Wr0) : (r < D ? Wl1 : Wr1);
    float v = W[(r & (D - 1)) * D + c];
    __half hi = __float2half_rn(v);
    __half lo = __float2half_rn(v - __half2float(hi));
    g_Whi[layer][rc] = hi;
    g_Wlo[layer][rc] = lo;
}

// ---------------- fp32 -> fp16 staging of features (per layer) ----------------
__global__ void to_half_kernel(const float* __restrict__ Xin, bool use_h1, int total2) {
    const float* __restrict__ X = use_h1 ? (const float*)g_h1 : Xin;
    int i = blockIdx.x * blockDim.x + threadIdx.x;
    if (i < total2) {
        float2 v = *(const float2*)(X + 2 * i);
        g_xh[i] = __floats2half2_rn(v.x, v.y);
    }
}

// ---------------- fused layer: out = elu(mean_nbr(X)@Wl + X@Wr + b) ----------------
// Phase A: 4 warps, 4 nodes/warp gather (fp16 rows) + mean; split into A_hi/A_lo smem (16 x 256).
// Phase B: wmma 3-pass split-fp16 GEMM 16x128xK256, W frags straight from global (L2).
__global__ void __launch_bounds__(NTHREADS)
fused_layer_kernel(const float* __restrict__ Xin, bool use_h1_in,
                   int layer,
                   const float* __restrict__ bias, // [128]
                   float* __restrict__ Out, bool write_h1,
                   int n)
{
    const float* __restrict__ X = use_h1_in ? (const float*)g_h1 : Xin;
    float* __restrict__ out     = write_h1  ? (float*)g_h1 : Out;

    __shared__ __half Ahi[TILE * K2];   // 8 KB
    __shared__ __half Alo[TILE * K2];   // 8 KB
    __shared__ float  Cs[TILE * D];     // 8 KB

    int tid  = threadIdx.x;
    int warp = tid >> 5;             // 0..3
    int lane = tid & 31;
    int row0 = blockIdx.x * TILE;

    // ---------- Phase A: gather (4 nodes per warp), fp16 rows ----------
    #pragma unroll
    for (int t = 0; t < 4; t++) {
        int rt   = (warp << 2) + t;      // row in tile 0..15
        int node = row0 + rt;
        float4 m = make_float4(0.f, 0.f, 0.f, 0.f);
        float4 sx = make_float4(0.f, 0.f, 0.f, 0.f);
        if (node < n) {
            int cnt = g_cnt[node];
            int e = cnt < CAP ? cnt : CAP;
            const int* __restrict__ bk = g_bucket + node * CAP;

            float ax = 0.f, ay = 0.f, az = 0.f, aw = 0.f;
            int i = 0;
            for (; i + 8 <= e; i += 8) {
                #pragma unroll
                for (int u = 0; u < 8; u++) {
                    int j = bk[i + u];
                    uint2 raw = *(const uint2*)(g_xh + (long long)j * (D / 2) + lane * 2);
                    __half2 h01 = *(__half2*)&raw.x;
                    __half2 h23 = *(__half2*)&raw.y;
                    float2 f01 = __half22float2(h01);
                    float2 f23 = __half22float2(h23);
                    ax += f01.x; ay += f01.y; az += f23.x; aw += f23.y;
                }
            }
            for (; i < e; i++) {
                int j = bk[i];
                uint2 raw = *(const uint2*)(g_xh + (long long)j * (D / 2) + lane * 2);
                __half2 h01 = *(__half2*)&raw.x;
                __half2 h23 = *(__half2*)&raw.y;
                float2 f01 = __half22float2(h01);
                float2 f23 = __half22float2(h23);
                ax += f01.x; ay += f01.y; az += f23.x; aw += f23.y;
            }
            // overflow edges (expected none)
            int novf = g_ovf_cnt;
            if (novf > 0) {
                if (novf > OVF_MAX) novf = OVF_MAX;
                for (int q = 0; q < novf; q++) {
                    if (g_ovf[2 * q + 1] == node) {
                        int j = g_ovf[2 * q];
                        uint2 raw = *(const uint2*)(g_xh + (long long)j * (D / 2) + lane * 2);
                        __half2 h01 = *(__half2*)&raw.x;
                        __half2 h23 = *(__half2*)&raw.y;
                        float2 f01 = __half22float2(h01);
                        float2 f23 = __half22float2(h23);
                        ax += f01.x; ay += f01.y; az += f23.x; aw += f23.y;
                    }
                }
            }
            float inv = 1.0f / (float)(cnt > 0 ? cnt : 1);
            m.x = ax * inv; m.y = ay * inv; m.z = az * inv; m.w = aw * inv;
            sx = *(const float4*)(X + (long long)node * D + lane * 4);
        }
        // split-write agg -> A cols [0,128), self -> A cols [128,256)
        float mv[4] = {m.x, m.y, m.z, m.w};
        float sv[4] = {sx.x, sx.y, sx.z, sx.w};
        #pragma unroll
        for (int c = 0; c < 4; c++) {
            __half hi = __float2half_rn(mv[c]);
            __half lo = __float2half_rn(mv[c] - __half2float(hi));
            Ahi[rt * K2 + lane * 4 + c] = hi;
            Alo[rt * K2 + lane * 4 + c] = lo;
            __half shi = __float2half_rn(sv[c]);
            __half slo = __float2half_rn(sv[c] - __half2float(shi));
            Ahi[rt * K2 + D + lane * 4 + c] = shi;
            Alo[rt * K2 + D + lane * 4 + c] = slo;
        }
    }
    __syncthreads();

    // ---------- Phase B: wmma split-fp16 GEMM, warp w covers cols [32w, 32w+32) ----------
    {
        const __half* __restrict__ Whi = g_Whi[layer];
        const __half* __restrict__ Wlo = g_Wlo[layer];
        int n0 = warp * 32;

        wmma::fragment<wmma::accumulator, 16, 16, 16, float> acc0, acc1;
        wmma::fill_fragment(acc0, 0.0f);
        wmma::fill_fragment(acc1, 0.0f);

        #pragma unroll
        for (int k0 = 0; k0 < K2; k0 += 16) {
            wmma::fragment<wmma::matrix_a, 16, 16, 16, __half, wmma::row_major> ah, al;
            wmma::load_matrix_sync(ah, Ahi + k0, K2);
            wmma::load_matrix_sync(al, Alo + k0, K2);

            wmma::fragment<wmma::matrix_b, 16, 16, 16, __half, wmma::row_major> bh, bl;
            // n-tile 0
            wmma::load_matrix_sync(bh, Whi + k0 * D + n0, D);
            wmma::load_matrix_sync(bl, Wlo + k0 * D + n0, D);
            wmma::mma_sync(acc0, ah, bh, acc0);
            wmma::mma_sync(acc0, ah, bl, acc0);
            wmma::mma_sync(acc0, al, bh, acc0);
            // n-tile 1
            wmma::load_matrix_sync(bh, Whi + k0 * D + n0 + 16, D);
            wmma::load_matrix_sync(bl, Wlo + k0 * D + n0 + 16, D);
            wmma::mma_sync(acc1, ah, bh, acc1);
            wmma::mma_sync(acc1, ah, bl, acc1);
            wmma::mma_sync(acc1, al, bh, acc1);
        }
        wmma::store_matrix_sync(Cs + n0, acc0, D, wmma::mem_row_major);
        wmma::store_matrix_sync(Cs + n0 + 16, acc1, D, wmma::mem_row_major);
    }
    __syncthreads();

    // ---------- epilogue: bias + ELU + store ----------
    int tx = tid & 31;   // col group: cols tx*4 .. tx*4+3
    int ty = tid >> 5;   // 0..3: rows ty + 4*r
    float4 bv = *(const float4*)(bias + tx * 4);
    #pragma unroll
    for (int r = 0; r < 4; r++) {
        int rt = ty + r * 4;
        int gr = row0 + rt;
        if (gr < n) {
            float4 o = *(const float4*)(Cs + rt * D + tx * 4);
            o.x += bv.x; o.y += bv.y; o.z += bv.z; o.w += bv.w;
            o.x = o.x > 0.f ? o.x : (__expf(o.x) - 1.0f);
            o.y = o.y > 0.f ? o.y : (__expf(o.y) - 1.0f);
            o.z = o.z > 0.f ? o.z : (__expf(o.z) - 1.0f);
            o.w = o.w > 0.f ? o.w : (__expf(o.w) - 1.0f);
            *(float4*)(out + (long long)gr * D + tx * 4) = o;
        }
    }
}

// ---------------- launch ----------------
extern "C" void kernel_launch(void* const* d_in, const int* in_sizes, int n_in,
                              void* d_out, int out_size) {
    const float* x   = (const float*)d_in[0];
    const int*   ei  = (const int*)d_in[1];      // int32 edge_index [2, E]
    const float* Wl0 = (const float*)d_in[2];
    const float* b0  = (const float*)d_in[3];
    const float* Wr0 = (const float*)d_in[4];
    const float* Wl1 = (const float*)d_in[5];
    const float* b1  = (const float*)d_in[6];
    const float* Wr1 = (const float*)d_in[7];
    float*       out = (float*)d_out;

    const int N = in_sizes[0] / D;          // 10000
    const int E = in_sizes[1] / 2;          // 640000
    const int total2 = N * (D / 2);         // 640000 half2 elements

    // bucket build + weight split (rebuilt every launch; deterministic)
    zero_kernel<<<(N + 255) / 256, 256>>>(N);
    scatter_kernel<<<(E + 255) / 256, 256>>>(ei, E, N);
    convert_w_kernel<<<(2 * K2 * D + 255) / 256, 256>>>(Wl0, Wr0, Wl1, Wr1);

    const int blocks = (N + TILE - 1) / TILE;      // 625
    const int convBlocks = (total2 + 255) / 256;

    // layer 0: stage x as fp16, fused agg+wmma-gemm -> g_h1
    to_half_kernel<<<convBlocks, 256>>>(x, false, total2);
    fused_layer_kernel<<<blocks, NTHREADS>>>(x, false, 0, b0, nullptr, true, N);
    // layer 1: stage g_h1 as fp16, fused agg+wmma-gemm -> d_out
    to_half_kernel<<<convBlocks, 256>>>(nullptr, true, total2);
    fused_layer_kernel<<<blocks, NTHREADS>>>(nullptr, true, 1, b1, out, false, N);
}